// round 12
// baseline (speedup 1.0000x reference)
#include <cuda_runtime.h>
#include <cuda_fp16.h>
#include <cstdint>

#define TOK   2048
#define DIMSZ 1024
#define HID   2048
#define NE    8
#define NSLOT (2 * TOK)

// Scratch (allocation-free: __device__ globals)
__device__ float g_w[NSLOT];
__device__ int   g_cnt[NE];
__device__ int   g_list[NE * TOK];
__device__ __align__(128) __half g_xh[TOK * DIMSZ];
__device__ __align__(128) __half g_wfch[NE * HID * DIMSZ];
__device__ __align__(128) __half g_wph[NE * DIMSZ * HID];
__device__ __align__(128) __half g_h2h[NSLOT * HID];
__device__ float g_y[(size_t)NSLOT * DIMSZ];

// ---------------------------------------------------------------------------
// Helpers
// ---------------------------------------------------------------------------
__device__ __forceinline__ uint32_t smem_u32(const void* p) {
    uint32_t a;
    asm("{ .reg .u64 t; cvta.to.shared.u64 t, %1; cvt.u32.u64 %0, t; }" : "=r"(a) : "l"(p));
    return a;
}
__device__ __forceinline__ void ldm4(uint32_t* r, uint32_t addr) {
    asm volatile("ldmatrix.sync.aligned.m8n8.x4.shared.b16 {%0,%1,%2,%3}, [%4];"
        : "=r"(r[0]), "=r"(r[1]), "=r"(r[2]), "=r"(r[3]) : "r"(addr));
}
__device__ __forceinline__ void mmaf16(float* c, const uint32_t* a, const uint32_t* b) {
    asm volatile(
        "mma.sync.aligned.m16n8k16.row.col.f32.f16.f16.f32 "
        "{%0,%1,%2,%3}, {%4,%5,%6,%7}, {%8,%9}, {%0,%1,%2,%3};"
        : "+f"(c[0]), "+f"(c[1]), "+f"(c[2]), "+f"(c[3])
        : "r"(a[0]), "r"(a[1]), "r"(a[2]), "r"(a[3]), "r"(b[0]), "r"(b[1]));
}
__device__ __forceinline__ void cp16(uint32_t dst, const void* src) {
    asm volatile("cp.async.cg.shared.global [%0], [%1], 16;" :: "r"(dst), "l"(src) : "memory");
}
__device__ __forceinline__ void cp_commit() {
    asm volatile("cp.async.commit_group;" ::: "memory");
}
template<int N> __device__ __forceinline__ void cp_wait() {
    asm volatile("cp.async.wait_group %0;" :: "n"(N) : "memory");
}
// SW128 swizzle for 128B rows: (row, 16B-chunk c in 0..7) -> byte offset
__device__ __forceinline__ uint32_t swz128(uint32_t row, uint32_t c) {
    return row * 128u + ((c ^ (row & 7u)) << 4);
}

// ---------------------------------------------------------------------------
__global__ void k_zero_counts() {
    if (threadIdx.x < NE) g_cnt[threadIdx.x] = 0;
}

// Convert fp32 -> fp16 for x, Wfc, Wp in ONE launch (flat index)
#define NX4 (TOK * DIMSZ / 4)
#define NF4 (NE * HID * DIMSZ / 4)
__global__ void k_cvt_all(const float4* __restrict__ x, const float4* __restrict__ wfc,
                          const float4* __restrict__ wp) {
    int i = blockIdx.x * 256 + threadIdx.x;
    const float4* s;
    uint2* d;
    int j;
    if (i < NX4)                 { s = x;   d = (uint2*)g_xh;   j = i; }
    else if (i < NX4 + NF4)      { s = wfc; d = (uint2*)g_wfch; j = i - NX4; }
    else if (i < NX4 + 2 * NF4)  { s = wp;  d = (uint2*)g_wph;  j = i - NX4 - NF4; }
    else return;
    float4 v = s[j];
    __half2 h0 = __floats2half2_rn(v.x, v.y);
    __half2 h1 = __floats2half2_rn(v.z, v.w);
    d[j] = make_uint2(*(uint32_t*)&h0, *(uint32_t*)&h1);
}

// Router: one warp per token. logits -> softmax -> top2 -> renormalize (+1e-8)
__global__ void k_router(const float* __restrict__ x, const float* __restrict__ Wr) {
    int warp = threadIdx.x >> 5;
    int lane = threadIdx.x & 31;
    int t = blockIdx.x * 8 + warp;

    float acc[NE];
#pragma unroll
    for (int e = 0; e < NE; ++e) acc[e] = 0.f;

    const float* xr = x + (size_t)t * DIMSZ;
    for (int i = lane; i < DIMSZ; i += 32) {
        float xv = xr[i];
#pragma unroll
        for (int e = 0; e < NE; ++e) acc[e] = fmaf(xv, Wr[e * DIMSZ + i], acc[e]);
    }
#pragma unroll
    for (int e = 0; e < NE; ++e) {
#pragma unroll
        for (int o = 16; o > 0; o >>= 1)
            acc[e] += __shfl_xor_sync(0xffffffffu, acc[e], o);
    }
    if (lane == 0) {
        float m = acc[0];
#pragma unroll
        for (int e = 1; e < NE; ++e) m = fmaxf(m, acc[e]);
        float p[NE]; float Z = 0.f;
#pragma unroll
        for (int e = 0; e < NE; ++e) { p[e] = expf(acc[e] - m); Z += p[e]; }
        float invZ = 1.f / Z;
#pragma unroll
        for (int e = 0; e < NE; ++e) p[e] *= invZ;

        int e0 = 0;
#pragma unroll
        for (int e = 1; e < NE; ++e) if (p[e] > p[e0]) e0 = e;
        int e1 = (e0 == 0) ? 1 : 0;
#pragma unroll
        for (int e = 0; e < NE; ++e) { if (e != e0 && p[e] > p[e1]) e1 = e; }

        float s = p[e0] + p[e1] + 1e-8f;
        g_w[2 * t]     = p[e0] / s;
        g_w[2 * t + 1] = p[e1] / s;
        int q0 = atomicAdd(&g_cnt[e0], 1); g_list[e0 * TOK + q0] = 2 * t;
        int q1 = atomicAdd(&g_cnt[e1], 1); g_list[e1 * TOK + q1] = 2 * t + 1;
    }
}

// ---------------------------------------------------------------------------
// Grouped GEMM: mma.sync m16n8k16 fp16 single-pass, fp32 accumulate.
// CTA = 128 threads (4 warps 2x2), tile 128x128, warp tile 64x64.
// K-slab = 64 fp16 (128B rows, SW128 swizzle). 3-stage cp.async pipeline,
// ONE __syncthreads per slab. Smem per stage: A mat + B mat, 16 KB each.
#define MAT      16384
#define STG      (2 * MAT)            // 32768
#define SLOT_OFF (3 * STG)            // 98304
#define AOFF_OFF (SLOT_OFF + 512)
#define GSMEM    (AOFF_OFF + 512)

template<int KDIM, int NDIM, bool RELU2, int SHIFT, int PHASE>
__global__ void __launch_bounds__(128, 2)
k_gemm_f16() {
    constexpr int NSLAB = KDIM / 64;
    const __half* Ahp = (PHASE == 1) ? g_xh : g_h2h;
    const __half* BA  = (PHASE == 1) ? g_wfch : g_wph;

    int e   = blockIdx.z;
    int cnt = g_cnt[e];
    int m0  = blockIdx.y * 128;
    if (m0 >= cnt) return;
    int n0  = blockIdx.x * 128;
    const __half* B = BA + (size_t)e * NDIM * KDIM;

    extern __shared__ char smem[];
    uint32_t sb = smem_u32(smem);
    int* s_slot = (int*)(smem + SLOT_OFF);
    int* s_aoff = (int*)(smem + AOFF_OFF);
    int tid = threadIdx.x, w = tid >> 5, lane = tid & 31;

    {
        int idx = m0 + tid;
        int sl  = g_list[e * TOK + ((idx < cnt) ? idx : m0)];
        s_slot[tid] = (idx < cnt) ? sl : -1;
        s_aoff[tid] = (sl >> SHIFT) * KDIM;
    }
    __syncthreads();

    // Loader: thread tid owns A row tid and B row (n0+tid); 8 chunks each
    const __half* arow = Ahp + s_aoff[tid];
    const __half* browp = B + (size_t)(n0 + tid) * KDIM;
    uint32_t dA = swz128((uint32_t)tid, 0) & ~0x7Fu;   // row base (chunk xor applied per j)

    auto issue = [&](int ks, int stage) {
        int k0 = ks * 64;
        uint32_t stg = sb + (uint32_t)stage * STG;
        uint32_t rb = stg + (uint32_t)tid * 128u;
        uint32_t r7 = (uint32_t)tid & 7u;
#pragma unroll
        for (int j = 0; j < 8; ++j) {
            uint32_t off = ((uint32_t)j ^ r7) << 4;
            cp16(rb + off,       arow + k0 + j * 8);
            cp16(rb + off + MAT, browp + k0 + j * 8);
        }
        cp_commit();
    };

    int wy = w >> 1, wx = w & 1;
    // ldmatrix per-lane base addresses for kk=0; kk in 0..3 via ^ (kk*0x20)
    uint32_t arow0 = (uint32_t)(wy * 64 + (lane & 15));
    uint32_t ahi   = (uint32_t)(lane >> 4);
    uint32_t aB0   = sb + arow0 * 128u + ((ahi ^ (arow0 & 7u)) << 4);
    uint32_t brow0 = (uint32_t)(wx * 64 + ((lane >> 4) & 1) * 8 + (lane & 7));
    uint32_t bhi   = (uint32_t)((lane >> 3) & 1);
    uint32_t bB0   = sb + MAT + brow0 * 128u + ((bhi ^ (brow0 & 7u)) << 4);

    float acc[4][8][4];
#pragma unroll
    for (int i = 0; i < 4; ++i)
#pragma unroll
        for (int j = 0; j < 8; ++j)
#pragma unroll
            for (int r = 0; r < 4; ++r) acc[i][j][r] = 0.f;

    issue(0, 0);
    issue(1, 1);
    cp_wait<1>();
    __syncthreads();

#pragma unroll 1
    for (int ks = 0; ks < NSLAB; ++ks) {
        int cur = ks % 3;
        if (ks + 2 < NSLAB) issue(ks + 2, (ks + 2) % 3);
        else                cp_commit();   // empty group keeps wait-count uniform

        uint32_t aS = aB0 + (uint32_t)cur * STG;
        uint32_t bS = bB0 + (uint32_t)cur * STG;
#pragma unroll
        for (int kk = 0; kk < 4; ++kk) {
            uint32_t ah[4][4], bb[4][4];
#pragma unroll
            for (int mt = 0; mt < 4; ++mt)
                ldm4(ah[mt], (aS + mt * 2048) ^ (kk * 0x20));
#pragma unroll
            for (int p = 0; p < 4; ++p)
                ldm4(bb[p], (bS + p * 2048) ^ (kk * 0x20));
#pragma unroll
            for (int mt = 0; mt < 4; ++mt)
#pragma unroll
                for (int nt = 0; nt < 8; ++nt)
                    mmaf16(acc[mt][nt], ah[mt], &bb[nt >> 1][(nt & 1) * 2]);
        }
        cp_wait<1>();      // slab ks+1 landed
        __syncthreads();   // stage cur free for refill next iteration
    }

    // Epilogue
    int rbase = wy * 64 + (lane >> 2);
    int cbase = n0 + wx * 64 + (lane & 3) * 2;
#pragma unroll
    for (int mt = 0; mt < 4; ++mt) {
#pragma unroll
        for (int half = 0; half < 2; ++half) {
            int sl = s_slot[rbase + mt * 16 + half * 8];
            if (sl < 0) continue;
            if (RELU2) {
                uint32_t* oh = (uint32_t*)(g_h2h + (size_t)sl * NDIM + cbase);
#pragma unroll
                for (int nt = 0; nt < 8; ++nt) {
                    float v0 = acc[mt][nt][half * 2 + 0];
                    float v1 = acc[mt][nt][half * 2 + 1];
                    v0 = fmaxf(v0, 0.f); v0 *= v0;
                    v1 = fmaxf(v1, 0.f); v1 *= v1;
                    __half2 hp = __floats2half2_rn(v0, v1);
                    oh[nt * 4] = *(uint32_t*)&hp;
                }
            } else {
                float* oy = g_y + (size_t)sl * NDIM + cbase;
#pragma unroll
                for (int nt = 0; nt < 8; ++nt) {
                    *(float2*)(oy + nt * 8) =
                        make_float2(acc[mt][nt][half * 2 + 0], acc[mt][nt][half * 2 + 1]);
                }
            }
        }
    }
}

// ---------------------------------------------------------------------------
__global__ void k_combine(float* __restrict__ out, int out_size) {
    int t = blockIdx.x;
    int i = threadIdx.x;
    float w0 = g_w[2 * t];
    float w1 = g_w[2 * t + 1];
    float4 a = ((const float4*)(g_y + (size_t)(2 * t) * DIMSZ))[i];
    float4 b = ((const float4*)(g_y + (size_t)(2 * t + 1) * DIMSZ))[i];
    float4 r;
    r.x = w0 * a.x + w1 * b.x;
    r.y = w0 * a.y + w1 * b.y;
    r.z = w0 * a.z + w1 * b.z;
    r.w = w0 * a.w + w1 * b.w;
    ((float4*)(out + (size_t)t * DIMSZ))[i] = r;
    if (t == 0 && i == 0) {
        for (int j = TOK * DIMSZ; j < out_size; ++j) out[j] = 0.f;  // aux_loss tail
    }
}

// ---------------------------------------------------------------------------
extern "C" void kernel_launch(void* const* d_in, const int* in_sizes, int n_in,
                              void* d_out, int out_size) {
    const float* x   = (const float*)d_in[0];   // [1, 2048, 1024]
    const float* Wr  = (const float*)d_in[1];   // [8, 1024]
    const float* Wfc = (const float*)d_in[2];   // [8, 2048, 1024]
    const float* Wp  = (const float*)d_in[3];   // [8, 1024, 2048]
    float* out = (float*)d_out;

    cudaFuncSetAttribute(k_gemm_f16<DIMSZ, HID, true, 1, 1>,
                         cudaFuncAttributeMaxDynamicSharedMemorySize, GSMEM);
    cudaFuncSetAttribute(k_gemm_f16<HID, DIMSZ, false, 0, 2>,
                         cudaFuncAttributeMaxDynamicSharedMemorySize, GSMEM);

    k_zero_counts<<<1, 32>>>();
    k_router<<<TOK / 8, 256>>>(x, Wr);
    k_cvt_all<<<(NX4 + 2 * NF4 + 255) / 256, 256>>>(
        (const float4*)x, (const float4*)Wfc, (const float4*)Wp);
    // GEMM1: h2[slot, H] = relu(x[tok] @ Wfc[e]^T)^2  (fp16 output)
    k_gemm_f16<DIMSZ, HID, true, 1, 1>
        <<<dim3(HID / 128, TOK / 128, NE), 128, GSMEM>>>();
    // GEMM2: y[slot, D] = h2[slot] @ Wp[e]^T
    k_gemm_f16<HID, DIMSZ, false, 0, 2>
        <<<dim3(DIMSZ / 128, TOK / 128, NE), 128, GSMEM>>>();
    k_combine<<<TOK, 256>>>(out, out_size);
}